// round 4
// baseline (speedup 1.0000x reference)
#include <cuda_runtime.h>

#define NTREES 128
#define C 8
#define L 2
#define M 256
#define G 4
#define NTH 1024

// Precomputed (softmaxed) parameters. SP folded into A.
// A layout: [c][d][p][g] (p interleaved). Bm: [c][m][g]. Pi: [p][c][g].
__device__ float g_A[C][C][L][G];
__device__ float g_Bm[C][M][G];
__device__ float g_Pi[L][C][G];

// ---------------- float2 helpers ----------------
static __device__ __forceinline__ float2 f2zero() { return make_float2(0.f, 0.f); }
static __device__ __forceinline__ float2 add2(float2 a, float2 b) {
    return make_float2(a.x + b.x, a.y + b.y);
}
static __device__ __forceinline__ float2 mul2(float2 a, float2 b) {
    return make_float2(a.x * b.x, a.y * b.y);
}
static __device__ __forceinline__ float2 fma2(float2 a, float2 b, float2 c) {
    return make_float2(fmaf(a.x, b.x, c.x), fmaf(a.y, b.y, c.y));
}
static __device__ __forceinline__ float2 rcp2(float2 a) {
    return make_float2(__fdividef(1.f, a.x), __fdividef(1.f, a.y));
}
static __device__ __forceinline__ float2 log2v(float2 a) {
    return make_float2(__logf(a.x), __logf(a.y));
}

// ---------------- precompute softmaxes (parallel) ----------------
__global__ void htmm_precompute(const float* __restrict__ lA, const float* __restrict__ lB,
                                const float* __restrict__ lPi, const float* __restrict__ lSP) {
    const int tid = threadIdx.x;
    const int wid = tid >> 5, lane = tid & 31;

    // Bm: one warp per (c,g)
    {
        int c = wid >> 2, g = wid & 3;
        float v[8];
        float mx = -1e30f;
#pragma unroll
        for (int j = 0; j < 8; j++) {
            int m = lane + 32 * j;
            v[j] = lB[(c * M + m) * G + g];
            mx = fmaxf(mx, v[j]);
        }
#pragma unroll
        for (int o = 16; o; o >>= 1) mx = fmaxf(mx, __shfl_xor_sync(0xffffffffu, mx, o));
        float s = 0.f;
#pragma unroll
        for (int j = 0; j < 8; j++) { v[j] = __expf(v[j] - mx); s += v[j]; }
#pragma unroll
        for (int o = 16; o; o >>= 1) s += __shfl_xor_sync(0xffffffffu, s, o);
        float r = 1.f / s;
#pragma unroll
        for (int j = 0; j < 8; j++) g_Bm[c][lane + 32 * j][g] = v[j] * r;
    }

    if (tid < 64) {
        // A: softmax over c per (d,p,g), fold SP[p,g]
        int d = tid >> 3, p = (tid >> 2) & 1, g = tid & 3;
        float s0 = lSP[0 * G + g], s1 = lSP[1 * G + g];
        float mxs = fmaxf(s0, s1);
        float e0 = __expf(s0 - mxs), e1 = __expf(s1 - mxs);
        float sp = (p == 0 ? e0 : e1) / (e0 + e1);
        float mx = -1e30f;
#pragma unroll
        for (int c = 0; c < C; c++) mx = fmaxf(mx, lA[((c * C + d) * L + p) * G + g]);
        float s = 0.f;
#pragma unroll
        for (int c = 0; c < C; c++) s += __expf(lA[((c * C + d) * L + p) * G + g] - mx);
        float r = sp / s;
#pragma unroll
        for (int c = 0; c < C; c++)
            g_A[c][d][p][g] = __expf(lA[((c * C + d) * L + p) * G + g] - mx) * r;
    } else if (tid < 72) {
        int t2 = tid - 64;
        int p = t2 >> 2, g = t2 & 3;
        float mx = -1e30f;
#pragma unroll
        for (int c = 0; c < C; c++) mx = fmaxf(mx, lPi[(c * L + p) * G + g]);
        float s = 0.f;
#pragma unroll
        for (int c = 0; c < C; c++) s += __expf(lPi[(c * L + p) * G + g] - mx);
        float r = 1.f / s;
#pragma unroll
        for (int c = 0; c < C; c++) g_Pi[p][c][g] = __expf(lPi[(c * L + p) * G + g] - mx) * r;
    }
}

// ---------------- main kernel: one CTA per tree, g split 2-way ----------------
// Thread = (gh, node): gh = tid>>9 handles g in {2gh, 2gh+1}; node = tid & 511.
// Transformed messages ping-pong per gh half.
// smem layout (float2 units):
//   bufA [0, 8192)      : [gh][c][512]  (levels 9,7,5,3,1)
//   bufB [8192, 12288)  : [gh][c][256]  (levels 8,6,4,2)
//   A_s  [12288, 12544) : [c][d][p][gh] float2
//   Bm_s [12544, 16640) : [c][m][gh]    float2
//   Pi_s [16640, 16672) : [p][c][gh]    float2
//   red  [16672, 16674) : 4 floats
#define SMEM_F2 16674
#define SMEM_BYTES (SMEM_F2 * 8)

__global__ __launch_bounds__(NTH) void htmm_main(const int* __restrict__ pos,
                                                 const int* __restrict__ x,
                                                 float* __restrict__ out) {
    extern __shared__ float2 sm2[];
    float2* bufA = sm2;              // per-gh stride 4096
    float2* bufB = sm2 + 8192;       // per-gh stride 2048
    float2* A_s  = sm2 + 12288;      // index: ((c*8+d)*2+p)*2 + gh
    float2* Bm_s = sm2 + 12544;      // index: (c*256+m)*2 + gh
    float2* Pi_s = sm2 + 16640;      // index: (p*8+c)*2 + gh
    float*  red  = (float*)(sm2 + 16672);

    const int t = blockIdx.x, tid = threadIdx.x;
    const int gh = tid >> 9, nd = tid & 511;

    // stage constants (as float4 chunks)
    {
        float4* smf4 = (float4*)sm2;
        if (tid < 128) smf4[6144 + tid] = ((const float4*)g_A)[tid];
        for (int i = tid; i < 2048; i += NTH) smf4[6272 + i] = ((const float4*)g_Bm)[i];
        if (tid < 16) smf4[8320 + tid] = ((const float4*)g_Pi)[tid];
        if (tid < 4) red[tid] = 0.f;
    }
    __syncthreads();

    float2* bufAh = bufA + gh * 4096;
    float2* bufBh = bufB + gh * 2048;

    float2 ll = f2zero();

    // ---- fused levels 11 -> 10 -> 9 in registers; thread = (l9 node, gh) ----
    {
        const int offL  = 128 * 2047 + (t << 11);
        const int off10 = 128 * 1023 + (t << 10);
        const int off9  = 128 * 511  + (t << 9);

        const int4 pL  = *(const int4*)(pos + offL + 4 * nd);
        const int4 xL  = *(const int4*)(x   + offL + 4 * nd);
        const int2 p10 = *(const int2*)(pos + off10 + 2 * nd);
        const int2 x10 = *(const int2*)(x   + off10 + 2 * nd);

        float2 acc9[8];
#pragma unroll
        for (int c = 0; c < 8; c++) acc9[c] = f2zero();

#pragma unroll
        for (int s10 = 0; s10 < 2; s10++) {
            float2 acc10[8];
#pragma unroll
            for (int c = 0; c < 8; c++) acc10[c] = f2zero();

#pragma unroll
            for (int s11 = 0; s11 < 2; s11++) {
                int li = 2 * s10 + s11;
                int p = (li == 0) ? pL.x : (li == 1) ? pL.y : (li == 2) ? pL.z : pL.w;
                int m = (li == 0) ? xL.x : (li == 1) ? xL.y : (li == 2) ? xL.z : xL.w;
                float2 b[8];
                float2 nu = f2zero();
#pragma unroll
                for (int c = 0; c < 8; c++) {
                    b[c] = mul2(Pi_s[(p * 8 + c) * 2 + gh], Bm_s[(c * 256 + m) * 2 + gh]);
                    nu = add2(nu, b[c]);
                }
                float2 r = rcp2(nu);
                ll = add2(ll, log2v(nu));
#pragma unroll
                for (int c = 0; c < 8; c++) b[c] = mul2(b[c], r);
                const float2* Ap = A_s + p * 2 + gh;
#pragma unroll
                for (int c = 0; c < 8; c++) {
                    float2 mm = f2zero();
#pragma unroll
                    for (int d = 0; d < 8; d++) mm = fma2(Ap[(c * 8 + d) * 4], b[d], mm);
                    acc10[c] = add2(acc10[c], mm);
                }
            }
            int m = (s10 == 0) ? x10.x : x10.y;
            int p = (s10 == 0) ? p10.x : p10.y;
            float2 nu = f2zero();
#pragma unroll
            for (int c = 0; c < 8; c++) {
                acc10[c] = mul2(acc10[c], Bm_s[(c * 256 + m) * 2 + gh]);
                nu = add2(nu, acc10[c]);
            }
            float2 r = rcp2(nu);
            ll = add2(ll, log2v(nu));
#pragma unroll
            for (int c = 0; c < 8; c++) acc10[c] = mul2(acc10[c], r);
            const float2* Ap = A_s + p * 2 + gh;
#pragma unroll
            for (int c = 0; c < 8; c++) {
                float2 mm = f2zero();
#pragma unroll
                for (int d = 0; d < 8; d++) mm = fma2(Ap[(c * 8 + d) * 4], acc10[d], mm);
                acc9[c] = add2(acc9[c], mm);
            }
        }
        // level-9 node: emit, normalize, transform, store message
        int m = x[off9 + nd];
        int p9 = pos[off9 + nd];
        float2 nu = f2zero();
#pragma unroll
        for (int c = 0; c < 8; c++) {
            acc9[c] = mul2(acc9[c], Bm_s[(c * 256 + m) * 2 + gh]);
            nu = add2(nu, acc9[c]);
        }
        float2 r = rcp2(nu);
        ll = add2(ll, log2v(nu));
#pragma unroll
        for (int c = 0; c < 8; c++) acc9[c] = mul2(acc9[c], r);
        const float2* Ap = A_s + p9 * 2 + gh;
#pragma unroll
        for (int c = 0; c < 8; c++) {
            float2 mm = f2zero();
#pragma unroll
            for (int d = 0; d < 8; d++) mm = fma2(Ap[(c * 8 + d) * 4], acc9[d], mm);
            bufAh[c * 512 + nd] = mm;
        }
    }
    __syncthreads();

    // ---- single-phase levels: l = child level (9,8,7), produce parents ----
#pragma unroll 1
    for (int l = 9; l >= 7; --l) {
        const int n_pa = 1 << (l - 1);            // 256, 128, 64
        float2* chb = (l & 1) ? bufAh : bufBh;
        const int cs = (l & 1) ? 512 : 256;
        float2* pb  = (l & 1) ? bufBh : bufAh;
        const int ps = (l & 1) ? 256 : 512;
        const int offP = 128 * ((1 << (l - 1)) - 1) + (t << (l - 1));

        if (nd < n_pa) {
            const int pa = nd;
            int m = x[offP + pa];
            int p = pos[offP + pa];
            float2 v[8];
            float2 nu = f2zero();
#pragma unroll
            for (int c = 0; c < 8; c++) {
                v[c] = add2(chb[c * cs + 2 * pa], chb[c * cs + 2 * pa + 1]);
                v[c] = mul2(v[c], Bm_s[(c * 256 + m) * 2 + gh]);
                nu = add2(nu, v[c]);
            }
            float2 r = rcp2(nu);
            ll = add2(ll, log2v(nu));
#pragma unroll
            for (int c = 0; c < 8; c++) v[c] = mul2(v[c], r);
            const float2* Ap = A_s + p * 2 + gh;
#pragma unroll
            for (int c = 0; c < 8; c++) {
                float2 mm = f2zero();
#pragma unroll
                for (int d = 0; d < 8; d++) mm = fma2(Ap[(c * 8 + d) * 4], v[d], mm);
                pb[c * ps + pa] = mm;
            }
        }
        __syncthreads();
    }

    // ---- tail: l = 6..1 (n_pa = 32..1), two independent warps (one per gh) ----
    if (nd < 32) {
#pragma unroll 1
        for (int l = 6; l >= 1; --l) {
            const int n_pa = 1 << (l - 1);
            float2* chb = (l & 1) ? bufAh : bufBh;
            const int cs = (l & 1) ? 512 : 256;
            float2* pb  = (l & 1) ? bufBh : bufAh;
            const int ps = (l & 1) ? 256 : 512;
            const int offP = 128 * ((1 << (l - 1)) - 1) + (t << (l - 1));

            if (nd < n_pa) {
                const int pa = nd;
                int m = x[offP + pa];
                float2 v[8];
                float2 nu = f2zero();
#pragma unroll
                for (int c = 0; c < 8; c++) {
                    v[c] = add2(chb[c * cs + 2 * pa], chb[c * cs + 2 * pa + 1]);
                    v[c] = mul2(v[c], Bm_s[(c * 256 + m) * 2 + gh]);
                    nu = add2(nu, v[c]);
                }
                ll = add2(ll, log2v(nu));
                if (l > 1) {
                    int p = pos[offP + pa];
                    float2 r = rcp2(nu);
#pragma unroll
                    for (int c = 0; c < 8; c++) v[c] = mul2(v[c], r);
                    const float2* Ap = A_s + p * 2 + gh;
#pragma unroll
                    for (int c = 0; c < 8; c++) {
                        float2 mm = f2zero();
#pragma unroll
                        for (int d = 0; d < 8; d++) mm = fma2(Ap[(c * 8 + d) * 4], v[d], mm);
                        pb[c * ps + pa] = mm;
                    }
                }
            }
            __syncwarp();
        }
    }

    // ---- reduction: warp shuffle (gh uniform per warp), then smem atomics ----
#pragma unroll
    for (int o = 16; o; o >>= 1) {
        ll.x += __shfl_xor_sync(0xffffffffu, ll.x, o);
        ll.y += __shfl_xor_sync(0xffffffffu, ll.y, o);
    }
    if ((tid & 31) == 0) {
        atomicAdd(&red[2 * gh + 0], ll.x);
        atomicAdd(&red[2 * gh + 1], ll.y);
    }
    __syncthreads();
    if (tid < 4) out[t * 4 + tid] = red[tid];
}

extern "C" void kernel_launch(void* const* d_in, const int* in_sizes, int n_in,
                              void* d_out, int out_size) {
    const float* lA  = (const float*)d_in[0];
    const float* lB  = (const float*)d_in[1];
    const float* lPi = (const float*)d_in[2];
    const float* lSP = (const float*)d_in[3];
    const int*   pos = (const int*)d_in[4];
    const int*   x   = (const int*)d_in[5];
    float*       out = (float*)d_out;

    cudaFuncSetAttribute(htmm_main, cudaFuncAttributeMaxDynamicSharedMemorySize, SMEM_BYTES);

    htmm_precompute<<<1, 1024>>>(lA, lB, lPi, lSP);
    htmm_main<<<NTREES, NTH, SMEM_BYTES>>>(pos, x, out);
}

// round 5
// speedup vs baseline: 1.0655x; 1.0655x over previous
#include <cuda_runtime.h>

#define NTREES 128
#define C 8
#define L 2
#define M 256
#define G 4
#define NTH 1024

typedef unsigned long long u64;

// Precomputed (softmaxed) parameters. SP folded into A.
__device__ float g_A[C][C][L][G];   // [c][d][p][g]
__device__ float g_Bm[C][M][G];
__device__ float g_Pi[L][C][G];

// ---------------- packed f32x2 helpers (sm_100+ FFMA2 path) ----------------
static __device__ __forceinline__ u64 pk2f(float lo, float hi) {
    u64 r; asm("mov.b64 %0,{%1,%2};" : "=l"(r) : "f"(lo), "f"(hi)); return r;
}
static __device__ __forceinline__ void unpk2f(u64 v, float& lo, float& hi) {
    asm("mov.b64 {%0,%1},%2;" : "=f"(lo), "=f"(hi) : "l"(v));
}
static __device__ __forceinline__ u64 fma2p(u64 a, u64 b, u64 c) {
    u64 d; asm("fma.rn.f32x2 %0,%1,%2,%3;" : "=l"(d) : "l"(a), "l"(b), "l"(c)); return d;
}
static __device__ __forceinline__ u64 mul2p(u64 a, u64 b) {
    u64 d; asm("mul.rn.f32x2 %0,%1,%2;" : "=l"(d) : "l"(a), "l"(b)); return d;
}
static __device__ __forceinline__ u64 add2p(u64 a, u64 b) {
    u64 d; asm("add.rn.f32x2 %0,%1,%2;" : "=l"(d) : "l"(a), "l"(b)); return d;
}

// ---------------- precompute softmaxes (parallel) ----------------
__global__ void htmm_precompute(const float* __restrict__ lA, const float* __restrict__ lB,
                                const float* __restrict__ lPi, const float* __restrict__ lSP) {
    const int tid = threadIdx.x;
    const int wid = tid >> 5, lane = tid & 31;

    // Bm: one warp per (c,g)
    {
        int c = wid >> 2, g = wid & 3;
        float v[8];
        float mx = -1e30f;
#pragma unroll
        for (int j = 0; j < 8; j++) {
            int m = lane + 32 * j;
            v[j] = lB[(c * M + m) * G + g];
            mx = fmaxf(mx, v[j]);
        }
#pragma unroll
        for (int o = 16; o; o >>= 1) mx = fmaxf(mx, __shfl_xor_sync(0xffffffffu, mx, o));
        float s = 0.f;
#pragma unroll
        for (int j = 0; j < 8; j++) { v[j] = __expf(v[j] - mx); s += v[j]; }
#pragma unroll
        for (int o = 16; o; o >>= 1) s += __shfl_xor_sync(0xffffffffu, s, o);
        float r = 1.f / s;
#pragma unroll
        for (int j = 0; j < 8; j++) g_Bm[c][lane + 32 * j][g] = v[j] * r;
    }

    if (tid < 64) {
        int d = tid >> 3, p = (tid >> 2) & 1, g = tid & 3;
        float s0 = lSP[0 * G + g], s1 = lSP[1 * G + g];
        float mxs = fmaxf(s0, s1);
        float e0 = __expf(s0 - mxs), e1 = __expf(s1 - mxs);
        float sp = (p == 0 ? e0 : e1) / (e0 + e1);
        float mx = -1e30f;
#pragma unroll
        for (int c = 0; c < C; c++) mx = fmaxf(mx, lA[((c * C + d) * L + p) * G + g]);
        float s = 0.f;
#pragma unroll
        for (int c = 0; c < C; c++) s += __expf(lA[((c * C + d) * L + p) * G + g] - mx);
        float r = sp / s;
#pragma unroll
        for (int c = 0; c < C; c++)
            g_A[c][d][p][g] = __expf(lA[((c * C + d) * L + p) * G + g] - mx) * r;
    } else if (tid < 72) {
        int t2 = tid - 64;
        int p = t2 >> 2, g = t2 & 3;
        float mx = -1e30f;
#pragma unroll
        for (int c = 0; c < C; c++) mx = fmaxf(mx, lPi[(c * L + p) * G + g]);
        float s = 0.f;
#pragma unroll
        for (int c = 0; c < C; c++) s += __expf(lPi[(c * L + p) * G + g] - mx);
        float r = 1.f / s;
#pragma unroll
        for (int c = 0; c < C; c++) g_Pi[p][c][g] = __expf(lPi[(c * L + p) * G + g] - mx) * r;
    }
}

// ---------------- main kernel: one CTA per tree, g split 2-way ----------------
// Thread = (gh, node): gh = tid>>9 handles g in {2gh, 2gh+1}; nd = tid & 511.
// smem map (u64 = packed float2 units):
//   bufA [0, 8192)      : [gh][c][512]  (levels 9,7,5,3,1)
//   bufB [8192, 12288)  : [gh][c][256]  (levels 8,6,4,2)
//   Bm_s [12288, 16384) : [gh][c][m]    (bank stride 8B in m -> fewer conflicts)
//   A_s  [16384, 16640) : [c][d][p][gh]
//   Pi_s [16640, 16672) : [p][c][gh]
//   red  [16672, 16674) : 4 floats
#define SMEM_U64 16674
#define SMEM_BYTES (SMEM_U64 * 8)

__global__ __launch_bounds__(NTH) void htmm_main(const int* __restrict__ pos,
                                                 const int* __restrict__ x,
                                                 float* __restrict__ out) {
    extern __shared__ u64 smu[];
    float* red = (float*)(smu + 16672);

    const int t = blockIdx.x, tid = threadIdx.x;
    const int gh = tid >> 9, nd = tid & 511;

    // stage constants
    if (tid < 128) {
        float4 f = ((const float4*)g_A)[tid];
        smu[16384 + 2 * tid]     = pk2f(f.x, f.y);
        smu[16384 + 2 * tid + 1] = pk2f(f.z, f.w);
    }
    for (int i = tid; i < 2048; i += NTH) {
        float4 f = ((const float4*)g_Bm)[i];
        smu[12288 + i] = pk2f(f.x, f.y);
        smu[14336 + i] = pk2f(f.z, f.w);
    }
    if (tid < 16) {
        float4 f = ((const float4*)g_Pi)[tid];
        smu[16640 + 2 * tid]     = pk2f(f.x, f.y);
        smu[16640 + 2 * tid + 1] = pk2f(f.z, f.w);
    }
    if (tid < 4) red[tid] = 0.f;
    __syncthreads();

    const u64* BmH = smu + 12288 + gh * 2048;   // [c*256 + m]
    const u64* A0  = smu + 16384 + gh;          // [(c*8+d)*4 + p*2]
    const u64* PiH = smu + 16640 + gh;          // [(p*8+c)*2]
    u64* bufAh = smu + gh * 4096;               // [c*512 + node]
    u64* bufBh = smu + 8192 + gh * 2048;        // [c*256 + node]

    float llx = 0.f, lly = 0.f;
    const u64 ONE2 = pk2f(1.f, 1.f);

    // ---- fused levels 11 -> 10 -> 9 in registers; thread = (l9 node, gh) ----
    {
        const int offL  = 128 * 2047 + (t << 11);
        const int off10 = 128 * 1023 + (t << 10);
        const int off9  = 128 * 511  + (t << 9);

        const int4 pL  = *(const int4*)(pos + offL + 4 * nd);
        const int4 xL  = *(const int4*)(x   + offL + 4 * nd);
        const int2 p10 = *(const int2*)(pos + off10 + 2 * nd);
        const int2 x10 = *(const int2*)(x   + off10 + 2 * nd);

        u64 acc9[8];
#pragma unroll
        for (int c = 0; c < 8; c++) acc9[c] = 0ull;

        u64 nuprodL = ONE2;   // product of 4 leaf nus
        u64 nuprodU = ONE2;   // product of 2 l10 nus + 1 l9 nu

#pragma unroll
        for (int s10 = 0; s10 < 2; s10++) {
            u64 acc10[8];
#pragma unroll
            for (int c = 0; c < 8; c++) acc10[c] = 0ull;

#pragma unroll
            for (int s11 = 0; s11 < 2; s11++) {
                int li = 2 * s10 + s11;
                int p = (li == 0) ? pL.x : (li == 1) ? pL.y : (li == 2) ? pL.z : pL.w;
                int m = (li == 0) ? xL.x : (li == 1) ? xL.y : (li == 2) ? xL.z : xL.w;
                u64 b[8];
                u64 nu;
#pragma unroll
                for (int c = 0; c < 8; c++) {
                    b[c] = mul2p(PiH[(p * 8 + c) * 2], BmH[c * 256 + m]);
                    nu = (c == 0) ? b[0] : add2p(nu, b[c]);
                }
                nuprodL = mul2p(nuprodL, nu);
                float nx, ny; unpk2f(nu, nx, ny);
                u64 r = pk2f(__fdividef(1.f, nx), __fdividef(1.f, ny));
#pragma unroll
                for (int c = 0; c < 8; c++) b[c] = mul2p(b[c], r);
                const u64* Ap = A0 + p * 2;
#pragma unroll
                for (int c = 0; c < 8; c++) {
#pragma unroll
                    for (int d = 0; d < 8; d++)
                        acc10[c] = fma2p(Ap[(c * 8 + d) * 4], b[d], acc10[c]);
                }
            }
            int m = (s10 == 0) ? x10.x : x10.y;
            int p = (s10 == 0) ? p10.x : p10.y;
            u64 nu;
#pragma unroll
            for (int c = 0; c < 8; c++) {
                acc10[c] = mul2p(acc10[c], BmH[c * 256 + m]);
                nu = (c == 0) ? acc10[0] : add2p(nu, acc10[c]);
            }
            nuprodU = mul2p(nuprodU, nu);
            float nx, ny; unpk2f(nu, nx, ny);
            u64 r = pk2f(__fdividef(1.f, nx), __fdividef(1.f, ny));
#pragma unroll
            for (int c = 0; c < 8; c++) acc10[c] = mul2p(acc10[c], r);
            const u64* Ap = A0 + p * 2;
#pragma unroll
            for (int c = 0; c < 8; c++) {
#pragma unroll
                for (int d = 0; d < 8; d++)
                    acc9[c] = fma2p(Ap[(c * 8 + d) * 4], acc10[d], acc9[c]);
            }
        }
        // level-9 node: emit, normalize, transform, store transformed message
        int m = x[off9 + nd];
        int p9 = pos[off9 + nd];
        u64 nu;
#pragma unroll
        for (int c = 0; c < 8; c++) {
            acc9[c] = mul2p(acc9[c], BmH[c * 256 + m]);
            nu = (c == 0) ? acc9[0] : add2p(nu, acc9[c]);
        }
        nuprodU = mul2p(nuprodU, nu);
        float nx, ny; unpk2f(nu, nx, ny);
        u64 r = pk2f(__fdividef(1.f, nx), __fdividef(1.f, ny));
#pragma unroll
        for (int c = 0; c < 8; c++) acc9[c] = mul2p(acc9[c], r);
        const u64* Ap = A0 + p9 * 2;
#pragma unroll
        for (int c = 0; c < 8; c++) {
            u64 mm = 0ull;
#pragma unroll
            for (int d = 0; d < 8; d++) mm = fma2p(Ap[(c * 8 + d) * 4], acc9[d], mm);
            bufAh[c * 512 + nd] = mm;
        }
        // batched logs
        float ax, ay, bx, by;
        unpk2f(nuprodL, ax, ay);
        unpk2f(nuprodU, bx, by);
        llx += __logf(ax) + __logf(bx);
        lly += __logf(ay) + __logf(by);
    }
    __syncthreads();

    // ---- single-phase levels: l = child level (9,8,7) ----
#pragma unroll 1
    for (int l = 9; l >= 7; --l) {
        const int n_pa = 1 << (l - 1);            // 256, 128, 64
        u64* chb = (l & 1) ? bufAh : bufBh;
        const int csh = (l & 1) ? 256 : 128;      // (stride/2) for ulonglong2 view
        u64* pb  = (l & 1) ? bufBh : bufAh;
        const int ps = (l & 1) ? 256 : 512;
        const int offP = 128 * ((1 << (l - 1)) - 1) + (t << (l - 1));

        if (nd < n_pa) {
            const int pa = nd;
            int m = x[offP + pa];
            int p = pos[offP + pa];
            const ulonglong2* ch2 = (const ulonglong2*)chb;
            u64 v[8];
            u64 nu;
#pragma unroll
            for (int c = 0; c < 8; c++) {
                ulonglong2 pr = ch2[c * csh + pa];
                v[c] = mul2p(add2p(pr.x, pr.y), BmH[c * 256 + m]);
                nu = (c == 0) ? v[0] : add2p(nu, v[c]);
            }
            float nx, ny; unpk2f(nu, nx, ny);
            llx += __logf(nx);
            lly += __logf(ny);
            u64 r = pk2f(__fdividef(1.f, nx), __fdividef(1.f, ny));
#pragma unroll
            for (int c = 0; c < 8; c++) v[c] = mul2p(v[c], r);
            const u64* Ap = A0 + p * 2;
#pragma unroll
            for (int c = 0; c < 8; c++) {
                u64 mm = 0ull;
#pragma unroll
                for (int d = 0; d < 8; d++) mm = fma2p(Ap[(c * 8 + d) * 4], v[d], mm);
                pb[c * ps + pa] = mm;
            }
        }
        __syncthreads();
    }

    // ---- tail: l = 6..1 (n_pa = 32..1), two independent warps (one per gh) ----
    if (nd < 32) {
        float prodx = 1.f, prody = 1.f;
#pragma unroll 1
        for (int l = 6; l >= 1; --l) {
            const int n_pa = 1 << (l - 1);
            u64* chb = (l & 1) ? bufAh : bufBh;
            const int csh = (l & 1) ? 256 : 128;
            u64* pb  = (l & 1) ? bufBh : bufAh;
            const int ps = (l & 1) ? 256 : 512;
            const int offP = 128 * ((1 << (l - 1)) - 1) + (t << (l - 1));

            if (nd < n_pa) {
                const int pa = nd;
                int m = x[offP + pa];
                const ulonglong2* ch2 = (const ulonglong2*)chb;
                u64 v[8];
                u64 nu;
#pragma unroll
                for (int c = 0; c < 8; c++) {
                    ulonglong2 pr = ch2[c * csh + pa];
                    v[c] = mul2p(add2p(pr.x, pr.y), BmH[c * 256 + m]);
                    nu = (c == 0) ? v[0] : add2p(nu, v[c]);
                }
                float nx, ny; unpk2f(nu, nx, ny);
                prodx *= nx; prody *= ny;
                if (l > 1) {
                    int p = pos[offP + pa];
                    u64 r = pk2f(__fdividef(1.f, nx), __fdividef(1.f, ny));
#pragma unroll
                    for (int c = 0; c < 8; c++) v[c] = mul2p(v[c], r);
                    const u64* Ap = A0 + p * 2;
#pragma unroll
                    for (int c = 0; c < 8; c++) {
                        u64 mm = 0ull;
#pragma unroll
                        for (int d = 0; d < 8; d++) mm = fma2p(Ap[(c * 8 + d) * 4], v[d], mm);
                        pb[c * ps + pa] = mm;
                    }
                }
            }
            __syncwarp();
        }
        llx += __logf(prodx);
        lly += __logf(prody);
    }

    // ---- reduction: warp shuffle (gh uniform per warp), then smem atomics ----
#pragma unroll
    for (int o = 16; o; o >>= 1) {
        llx += __shfl_xor_sync(0xffffffffu, llx, o);
        lly += __shfl_xor_sync(0xffffffffu, lly, o);
    }
    if ((tid & 31) == 0) {
        atomicAdd(&red[2 * gh + 0], llx);
        atomicAdd(&red[2 * gh + 1], lly);
    }
    __syncthreads();
    if (tid < 4) out[t * 4 + tid] = red[tid];
}

extern "C" void kernel_launch(void* const* d_in, const int* in_sizes, int n_in,
                              void* d_out, int out_size) {
    const float* lA  = (const float*)d_in[0];
    const float* lB  = (const float*)d_in[1];
    const float* lPi = (const float*)d_in[2];
    const float* lSP = (const float*)d_in[3];
    const int*   pos = (const int*)d_in[4];
    const int*   x   = (const int*)d_in[5];
    float*       out = (float*)d_out;

    cudaFuncSetAttribute(htmm_main, cudaFuncAttributeMaxDynamicSharedMemorySize, SMEM_BYTES);

    htmm_precompute<<<1, 1024>>>(lA, lB, lPi, lSP);
    htmm_main<<<NTREES, NTH, SMEM_BYTES>>>(pos, x, out);
}